// round 15
// baseline (speedup 1.0000x reference)
#include <cuda_runtime.h>
#include <cuda_fp16.h>
#include <math.h>
#include <stdint.h>

#define BB 2
#define SS 2048
#define DM 1024
#define NH 16
#define HD 64
#define MT (BB*SS)   // 4096 rows total

// Scratch (allocation-free), fp16 storage.
__device__ __half g_a16[MT*DM];          // states
__device__ __half g_w16[4*DM*DM];        // Wq|Wk|Wv|Wo
__device__ __half g_q[BB*NH*SS*HD];      // tanh(qkv)
__device__ __half g_k[BB*NH*SS*HD];
__device__ __half g_v[BB*NH*SS*HD];
__device__ __half g_ctx[MT*DM];          // attention out

__device__ __forceinline__ uint32_t smem_u32(const void* p) {
    uint32_t a;
    asm("{ .reg .u64 t; cvta.to.shared.u64 t, %1; cvt.u32.u64 %0, t; }"
        : "=r"(a) : "l"(p));
    return a;
}

__device__ __forceinline__ void mma_f16(float* c, const uint32_t* a,
                                        uint32_t b0, uint32_t b1) {
    asm volatile(
        "mma.sync.aligned.m16n8k16.row.col.f32.f16.f16.f32 "
        "{%0,%1,%2,%3},{%4,%5,%6,%7},{%8,%9},{%0,%1,%2,%3};\n"
        : "+f"(c[0]), "+f"(c[1]), "+f"(c[2]), "+f"(c[3])
        : "r"(a[0]), "r"(a[1]), "r"(a[2]), "r"(a[3]), "r"(b0), "r"(b1));
}

__device__ __forceinline__ void ldsm_x4(uint32_t* r, uint32_t saddr) {
    asm volatile(
        "ldmatrix.sync.aligned.m8n8.x4.shared.b16 {%0,%1,%2,%3}, [%4];"
        : "=r"(r[0]), "=r"(r[1]), "=r"(r[2]), "=r"(r[3])
        : "r"(saddr));
}
__device__ __forceinline__ void ldsm_x4_t(uint32_t* r, uint32_t saddr) {
    asm volatile(
        "ldmatrix.sync.aligned.m8n8.x4.trans.shared.b16 {%0,%1,%2,%3}, [%4];"
        : "=r"(r[0]), "=r"(r[1]), "=r"(r[2]), "=r"(r[3])
        : "r"(saddr));
}

__device__ __forceinline__ uint32_t pack_h2(float lo, float hi) {
    __half2 h = __floats2half2_rn(lo, hi);
    return *reinterpret_cast<uint32_t*>(&h);
}

#define CP16(dst, src) \
    asm volatile("cp.async.cg.shared.global [%0], [%1], 16;" \
                 :: "r"(dst), "l"(src))
#define CP_COMMIT() asm volatile("cp.async.commit_group;" ::: "memory")
#define CP_WAIT(n)  asm volatile("cp.async.wait_group %0;" :: "n"(n) : "memory")

// ---------------------------------------------------------------------------
// Pre-convert: states + 4 weights -> fp16.
// ---------------------------------------------------------------------------
__global__ void __launch_bounds__(256) convert_inputs(
    const float* __restrict__ states,
    const float* __restrict__ Wq, const float* __restrict__ Wk,
    const float* __restrict__ Wv, const float* __restrict__ Wo)
{
    size_t idx = (size_t)blockIdx.x * blockDim.x + threadIdx.x;  // float4 idx
    const float* src;
    __half* dst;
    size_t off;
    if (idx < 1048576) {
        src = states; dst = g_a16; off = idx;
    } else {
        size_t j = idx - 1048576;
        int w = (int)(j >> 18);
        off = j & 262143;
        src = (w == 0) ? Wq : (w == 1) ? Wk : (w == 2) ? Wv : Wo;
        dst = g_w16 + (size_t)w * 1048576;
    }
    float4 v = *(const float4*)(src + off * 4);
    uint2 u = make_uint2(pack_h2(v.x, v.y), pack_h2(v.z, v.w));
    *(uint2*)(dst + off * 4) = u;
}

// ---------------------------------------------------------------------------
// FP16 tensor-core GEMM: C = tanh(A @ W + bias).
// CTA tile 128x128, K-step 32, 5-stage cp.async (3 loads in flight during
// compute), 8 warps (2x4) 64x32. A frags: ldmatrix.x4 (stride 40 halfs,
// conflict-free). B frags: ldmatrix.x4.trans on [k][n] tile (stride 136).
// ---------------------------------------------------------------------------
#define ASTR 40
#define BSTR 136
#define STAGES 5
#define A_STG (128 * ASTR)               // halfs (10240 B)
#define B_STG (32 * BSTR)                // halfs (8704 B)
#define GEMM_SMEM (STAGES * (A_STG + B_STG) * 2)   // 94720 B

template<int MODE>
__global__ void __launch_bounds__(256, 2) gemm_f16_bias_tanh(
    const __half* __restrict__ Abase,
    const float* __restrict__ bq, const float* __restrict__ bk,
    const float* __restrict__ bv,
    float* __restrict__ outO)
{
    extern __shared__ __half hsm[];
    __half* smA = hsm;
    __half* smB = hsm + STAGES * A_STG;
    const uint32_t smA_u = smem_u32(smA);
    const uint32_t smB_u = smem_u32(smB);

    const __half* W;
    const float* bias;
    __half* outq;
    if (MODE == 0) {
        int z = blockIdx.z;
        W    = g_w16 + (size_t)z * (DM * DM);
        bias = (z == 0) ? bq : (z == 1) ? bk : bv;
        outq = (z == 0) ? g_q : (z == 1) ? g_k : g_v;
    } else {
        W = g_w16 + (size_t)3 * (DM * DM);
        bias = bq;
        outq = nullptr;
    }

    const int tid  = threadIdx.x;
    const int wid  = tid >> 5;
    const int lane = tid & 31;
    const int grp  = lane >> 2;
    const int q    = lane & 3;
    const int wm   = wid & 1;
    const int wn   = wid >> 1;

    const int bm = blockIdx.y * 128;
    const int bn = blockIdx.x * 128;

    // Staging: A 128x32 halfs = 512 16B-chunks; B 32x128 halfs = 512 chunks.
    const int a_row0 = tid >> 2, a_c = (tid & 3) * 8;
    const int b_r0   = tid >> 4, b_c8 = (tid & 15) * 8;

    const __half* Ap0 = Abase + (size_t)(bm + a_row0) * DM + a_c;
    const __half* Ap1 = Abase + (size_t)(bm + a_row0 + 64) * DM + a_c;
    const __half* Wp0 = W + (size_t)b_r0 * DM + bn + b_c8;
    const __half* Wp1 = W + (size_t)(b_r0 + 16) * DM + bn + b_c8;

    const uint32_t aoff0 = (uint32_t)((a_row0 * ASTR + a_c) * 2);
    const uint32_t aoff1 = (uint32_t)(((a_row0 + 64) * ASTR + a_c) * 2);
    const uint32_t boff0 = (uint32_t)((b_r0 * BSTR + b_c8) * 2);
    const uint32_t boff1 = (uint32_t)(((b_r0 + 16) * BSTR + b_c8) * 2);

    // ldmatrix lane addresses
    const uint32_t aFragOff = (uint32_t)(((wm * 64 + (lane & 15)) * ASTR
                                          + (lane >> 4) * 8) * 2);
    const uint32_t bLaneOff = (uint32_t)(((((lane >> 3) & 1) * 8 + (lane & 7)) * BSTR
                                          + (lane >> 4) * 8) * 2);

    float acc[4][4][4];
    #pragma unroll
    for (int i = 0; i < 4; i++)
        #pragma unroll
        for (int j = 0; j < 4; j++)
            #pragma unroll
            for (int r = 0; r < 4; r++) acc[i][j][r] = 0.f;

    #pragma unroll
    for (int s = 0; s < STAGES - 1; s++) {
        uint32_t aB = smA_u + (uint32_t)(s * A_STG * 2);
        uint32_t bB = smB_u + (uint32_t)(s * B_STG * 2);
        const int k0 = s * 32;
        CP16(aB + aoff0, Ap0 + k0);
        CP16(aB + aoff1, Ap1 + k0);
        CP16(bB + boff0, Wp0 + (size_t)k0 * DM);
        CP16(bB + boff1, Wp1 + (size_t)k0 * DM);
        CP_COMMIT();
    }

    for (int i = 0; i < DM / 32; i++) {
        CP_WAIT(3);
        __syncthreads();

        int pre = i + STAGES - 1;
        if (pre < DM / 32) {
            int s = pre % STAGES;
            uint32_t aB = smA_u + (uint32_t)(s * A_STG * 2);
            uint32_t bB = smB_u + (uint32_t)(s * B_STG * 2);
            const int k0 = pre * 32;
            CP16(aB + aoff0, Ap0 + k0);
            CP16(aB + aoff1, Ap1 + k0);
            CP16(bB + boff0, Wp0 + (size_t)k0 * DM);
            CP16(bB + boff1, Wp1 + (size_t)k0 * DM);
        }
        CP_COMMIT();

        const int st = i % STAGES;
        const uint32_t aAddr = smA_u + (uint32_t)(st * A_STG * 2) + aFragOff;
        const uint32_t bAddr = smB_u + (uint32_t)(st * B_STG * 2) + bLaneOff;
        #pragma unroll
        for (int kk = 0; kk < 32; kk += 16) {
            uint32_t af[4][4];
            #pragma unroll
            for (int im = 0; im < 4; im++)
                ldsm_x4(af[im], aAddr + (uint32_t)((im * 16 * ASTR + kk) * 2));
            uint32_t bf[2][4];   // [half16][4 regs = b0/b1 for 2 n-blocks]
            #pragma unroll
            for (int hh = 0; hh < 2; hh++)
                ldsm_x4_t(bf[hh], bAddr + (uint32_t)((kk * BSTR
                                   + wn * 32 + hh * 16) * 2));
            #pragma unroll
            for (int im = 0; im < 4; im++) {
                mma_f16(acc[im][0], af[im], bf[0][0], bf[0][1]);
                mma_f16(acc[im][1], af[im], bf[0][2], bf[0][3]);
                mma_f16(acc[im][2], af[im], bf[1][0], bf[1][1]);
                mma_f16(acc[im][3], af[im], bf[1][2], bf[1][3]);
            }
        }
    }

    #pragma unroll
    for (int im = 0; im < 4; im++) {
        #pragma unroll
        for (int in_ = 0; in_ < 4; in_++) {
            int n0 = bn + wn * 32 + in_ * 8 + 2 * q;
            float b0v = bias[n0], b1v = bias[n0 + 1];
            #pragma unroll
            for (int half = 0; half < 2; half++) {
                int m = bm + wm * 64 + im * 16 + grp + half * 8;
                float y0 = tanhf(acc[im][in_][half * 2 + 0] + b0v);
                float y1 = tanhf(acc[im][in_][half * 2 + 1] + b1v);
                if (MODE == 0) {
                    int bbi = m >> 11;
                    int s   = m & 2047;
                    int h0  = n0 >> 6;
                    int d0  = n0 & 63;
                    size_t base = (((size_t)bbi * NH + h0) * SS + s) * HD + d0;
                    *reinterpret_cast<__half2*>(&outq[base]) =
                        __floats2half2_rn(y0, y1);
                } else {
                    outO[(size_t)m * DM + n0]     = y0;
                    outO[(size_t)m * DM + n0 + 1] = y1;
                }
            }
        }
    }
}

// ---------------------------------------------------------------------------
// FP16 causal flash attention (R12 config). Double-buffered 128-row K/V
// tiles via cp.async; each tile computed as two 64-row halves between ONE
// sync pair. f32 accumulation; P packs from S C-frag.
// Smem = Q[128] + 2x(K[128]+V[128]) @ stride 72 = 90KB -> 2 CTAs/SM.
// ---------------------------------------------------------------------------
#define QSTR 72
#define KVSTR 72
#define Q_H (128 * QSTR)
#define KV_H (128 * KVSTR)
#define SMEM_ATTN ((Q_H + 4 * KV_H) * 2)

__global__ void __launch_bounds__(256, 2) flash_attn_f16()
{
    extern __shared__ __half smh[];

    const int tid  = threadIdx.x;
    const int wid  = tid >> 5;
    const int lane = tid & 31;
    const int grp  = lane >> 2;
    const int qq   = lane & 3;
    const int qt   = (gridDim.x - 1) - blockIdx.x;
    const int h    = blockIdx.y;
    const int b    = blockIdx.z;
    const int q0   = qt * 128;
    const int mb   = wid * 16;

    const size_t head_off = ((size_t)(b * NH + h)) * SS * HD;
    const __half* Qg = g_q + head_off;
    const __half* Kg = g_k + head_off;
    const __half* Vg = g_v + head_off;

    const uint32_t sbase = smem_u32(smh);
    const uint32_t kBuf[2] = { sbase + Q_H * 2, sbase + (Q_H + KV_H) * 2 };
    const uint32_t vBuf[2] = { sbase + (Q_H + 2 * KV_H) * 2,
                               sbase + (Q_H + 3 * KV_H) * 2 };

    const uint32_t qLane = sbase + (uint32_t)(((mb + (lane & 15)) * QSTR
                                               + (lane >> 4) * 8) * 2);
    const uint32_t kLaneOff = (uint32_t)(((((lane >> 4) & 1) * 8 + (lane & 7)) * KVSTR
                                          + ((lane >> 3) & 1) * 8) * 2);
    const uint32_t vLaneOff = (uint32_t)(((((lane >> 3) & 1) * 8 + (lane & 7)) * KVSTR
                                          + (lane >> 4) * 8) * 2);

    for (int i = tid; i < 1024; i += 256) {
        int r = i >> 3, c8 = (i & 7) * 8;
        CP16(sbase + (uint32_t)((r * QSTR + c8) * 2),
             Qg + (size_t)(q0 + r) * HD + c8);
    }
    CP_COMMIT();

    for (int i = tid; i < 1024; i += 256) {
        int r = i >> 3, c8 = (i & 7) * 8;
        const size_t src = (size_t)r * HD + c8;
        CP16(kBuf[0] + (uint32_t)((r * KVSTR + c8) * 2), Kg + src);
        CP16(vBuf[0] + (uint32_t)((r * KVSTR + c8) * 2), Vg + src);
    }
    CP_COMMIT();

    float m0 = -1e30f, m1 = -1e30f, l0 = 0.f, l1 = 0.f;
    float o[8][4];
    #pragma unroll
    for (int nf = 0; nf < 8; nf++)
        #pragma unroll
        for (int r = 0; r < 4; r++) o[nf][r] = 0.f;

    const int n_kt = qt + 1;
    const int row0 = q0 + mb + grp;
    const int row1 = row0 + 8;

    for (int kt = 0; kt < n_kt; kt++) {
        const int buf = kt & 1;
        const bool has_next = (kt + 1 < n_kt);

        __syncthreads();

        if (has_next) {
            const int r0n = (kt + 1) * 128;
            const int nb = buf ^ 1;
            for (int i = tid; i < 1024; i += 256) {
                int r = i >> 3, c8 = (i & 7) * 8;
                const size_t src = (size_t)(r0n + r) * HD + c8;
                CP16(kBuf[nb] + (uint32_t)((r * KVSTR + c8) * 2), Kg + src);
                CP16(vBuf[nb] + (uint32_t)((r * KVSTR + c8) * 2), Vg + src);
            }
            CP_COMMIT();
            CP_WAIT(1);
        } else {
            CP_WAIT(0);
        }
        __syncthreads();

        #pragma unroll
        for (int hi = 0; hi < 2; hi++) {
            const int k0h = kt * 128 + hi * 64;
            if (k0h > q0 + mb + 15) continue;

            float sc[8][4];
            #pragma unroll
            for (int nf = 0; nf < 8; nf++)
                #pragma unroll
                for (int r = 0; r < 4; r++) sc[nf][r] = 0.f;

            const uint32_t kLane = kBuf[buf] + (uint32_t)(hi * 64 * KVSTR * 2)
                                 + kLaneOff;
            #pragma unroll
            for (int kf = 0; kf < 4; kf++) {
                uint32_t a[4];
                ldsm_x4(a, qLane + (uint32_t)(kf * 32));
                #pragma unroll
                for (int nf2 = 0; nf2 < 8; nf2 += 2) {
                    uint32_t kb[4];
                    ldsm_x4(kb, kLane + (uint32_t)((nf2 * 8 * KVSTR) * 2 + kf * 32));
                    mma_f16(sc[nf2],     a, kb[0], kb[1]);
                    mma_f16(sc[nf2 + 1], a, kb[2], kb[3]);
                }
            }

            const bool diag = (k0h + 63 > q0 + mb);
            float rm0 = -1e30f, rm1 = -1e30f;
            #pragma unroll
            for (int nf = 0; nf < 8; nf++) {
                int c0 = k0h + nf * 8 + 2 * qq;
                float s0v = sc[nf][0] * 0.125f;
                float s1v = sc[nf][1] * 0.125f;
                float s2v = sc[nf][2] * 0.125f;
                float s3v = sc[nf][3] * 0.125f;
                if (diag) {
                    if (c0     > row0) s0v = -1e30f;
                    if (c0 + 1 > row0) s1v = -1e30f;
                    if (c0     > row1) s2v = -1e30f;
                    if (c0 + 1 > row1) s3v = -1e30f;
                }
                sc[nf][0] = s0v; sc[nf][1] = s1v; sc[nf][2] = s2v; sc[nf][3] = s3v;
                rm0 = fmaxf(rm0, fmaxf(s0v, s1v));
                rm1 = fmaxf(rm1, fmaxf(s2v, s3v));
            }
            #pragma unroll
            for (int off = 1; off <= 2; off <<= 1) {
                rm0 = fmaxf(rm0, __shfl_xor_sync(0xffffffffu, rm0, off));
                rm1 = fmaxf(rm1, __shfl_xor_sync(0xffffffffu, rm1, off));
            }
            float mn0 = fmaxf(m0, rm0);
            float mn1 = fmaxf(m1, rm1);

            float s0 = 0.f, s1 = 0.f;
            #pragma unroll
            for (int nf = 0; nf < 8; nf++) {
                float p0 = __expf(sc[nf][0] - mn0);
                float p1 = __expf(sc[nf][1] - mn0);
                float p2 = __expf(sc[nf][2] - mn1);
                float p3 = __expf(sc[nf][3] - mn1);
                sc[nf][0] = p0; sc[nf][1] = p1; sc[nf][2] = p2; sc[nf][3] = p3;
                s0 += p0 + p1;
                s1 += p2 + p3;
            }
            #pragma unroll
            for (int off = 1; off <= 2; off <<= 1) {
                s0 += __shfl_xor_sync(0xffffffffu, s0, off);
                s1 += __shfl_xor_sync(0xffffffffu, s1, off);
            }
            float a0 = __expf(m0 - mn0);
            float a1 = __expf(m1 - mn1);
            l0 = l0 * a0 + s0;
            l1 = l1 * a1 + s1;
            m0 = mn0; m1 = mn1;
            #pragma unroll
            for (int nf = 0; nf < 8; nf++) {
                o[nf][0] *= a0; o[nf][1] *= a0;
                o[nf][2] *= a1; o[nf][3] *= a1;
            }

            const uint32_t vLane = vBuf[buf] + (uint32_t)(hi * 64 * KVSTR * 2)
                                 + vLaneOff;
            #pragma unroll
            for (int kf = 0; kf < 4; kf++) {
                uint32_t a[4];
                a[0] = pack_h2(sc[2*kf][0],   sc[2*kf][1]);
                a[1] = pack_h2(sc[2*kf][2],   sc[2*kf][3]);
                a[2] = pack_h2(sc[2*kf+1][0], sc[2*kf+1][1]);
                a[3] = pack_h2(sc[2*kf+1][2], sc[2*kf+1][3]);
                #pragma unroll
                for (int nf2 = 0; nf2 < 8; nf2 += 2) {
                    uint32_t vb[4];
                    ldsm_x4_t(vb, vLane + (uint32_t)((kf * 16 * KVSTR + nf2 * 8) * 2));
                    mma_f16(o[nf2],     a, vb[0], vb[1]);
                    mma_f16(o[nf2 + 1], a, vb[2], vb[3]);
                }
            }
        }
    }

    float inv0 = 1.f / l0;
    float inv1 = 1.f / l1;
    #pragma unroll
    for (int nf = 0; nf < 8; nf++) {
        int c = h * HD + nf * 8 + 2 * qq;
        *reinterpret_cast<__half2*>(&g_ctx[((size_t)b * SS + row0) * DM + c]) =
            __floats2half2_rn(o[nf][0] * inv0, o[nf][1] * inv0);
        *reinterpret_cast<__half2*>(&g_ctx[((size_t)b * SS + row1) * DM + c]) =
            __floats2half2_rn(o[nf][2] * inv1, o[nf][3] * inv1);
    }
}

// ---------------------------------------------------------------------------
extern "C" void kernel_launch(void* const* d_in, const int* in_sizes, int n_in,
                              void* d_out, int out_size)
{
    const float* states = (const float*)d_in[0];
    const float* Wq = (const float*)d_in[1];
    const float* bq = (const float*)d_in[2];
    const float* Wk = (const float*)d_in[3];
    const float* bk = (const float*)d_in[4];
    const float* Wv = (const float*)d_in[5];
    const float* bv = (const float*)d_in[6];
    const float* bo = (const float*)d_in[8];
    float* out = (float*)d_out;

    __half* a16_ptr = nullptr;
    __half* ctx_ptr = nullptr;
    cudaGetSymbolAddress((void**)&a16_ptr, g_a16);
    cudaGetSymbolAddress((void**)&ctx_ptr, g_ctx);

    cudaFuncSetAttribute(gemm_f16_bias_tanh<0>,
                         cudaFuncAttributeMaxDynamicSharedMemorySize, GEMM_SMEM);
    cudaFuncSetAttribute(gemm_f16_bias_tanh<1>,
                         cudaFuncAttributeMaxDynamicSharedMemorySize, GEMM_SMEM);
    cudaFuncSetAttribute(flash_attn_f16,
                         cudaFuncAttributeMaxDynamicSharedMemorySize, SMEM_ATTN);

    // 0) convert inputs to fp16
    convert_inputs<<<8192, 256>>>(states, Wq, Wk, Wv, (const float*)d_in[7]);

    // 1) QKV projections
    dim3 gq(DM / 128, MT / 128, 3);
    gemm_f16_bias_tanh<0><<<gq, 256, GEMM_SMEM>>>(a16_ptr, bq, bk, bv, nullptr);

    // 2) causal flash attention
    dim3 ga(SS / 128, NH, BB);
    flash_attn_f16<<<ga, 256, SMEM_ATTN>>>();

    // 3) output projection
    dim3 go(DM / 128, MT / 128, 1);
    gemm_f16_bias_tanh<1><<<go, 256, GEMM_SMEM>>>(ctx_ptr, bo, nullptr, nullptr, out);
}

// round 16
// speedup vs baseline: 1.0164x; 1.0164x over previous
#include <cuda_runtime.h>
#include <cuda_fp16.h>
#include <math.h>
#include <stdint.h>

#define BB 2
#define SS 2048
#define DM 1024
#define NH 16
#define HD 64
#define MT (BB*SS)   // 4096 rows total

// Scratch (allocation-free), fp16 storage.
__device__ __half g_a16[MT*DM];          // states
__device__ __half g_w16[4*DM*DM];        // Wq|Wk|Wv|Wo
__device__ __half g_q[BB*NH*SS*HD];      // tanh(qkv)
__device__ __half g_k[BB*NH*SS*HD];
__device__ __half g_v[BB*NH*SS*HD];
__device__ __half g_ctx[MT*DM];          // attention out

__device__ __forceinline__ uint32_t smem_u32(const void* p) {
    uint32_t a;
    asm("{ .reg .u64 t; cvta.to.shared.u64 t, %1; cvt.u32.u64 %0, t; }"
        : "=r"(a) : "l"(p));
    return a;
}

__device__ __forceinline__ void mma_f16(float* c, const uint32_t* a,
                                        uint32_t b0, uint32_t b1) {
    asm volatile(
        "mma.sync.aligned.m16n8k16.row.col.f32.f16.f16.f32 "
        "{%0,%1,%2,%3},{%4,%5,%6,%7},{%8,%9},{%0,%1,%2,%3};\n"
        : "+f"(c[0]), "+f"(c[1]), "+f"(c[2]), "+f"(c[3])
        : "r"(a[0]), "r"(a[1]), "r"(a[2]), "r"(a[3]), "r"(b0), "r"(b1));
}

__device__ __forceinline__ void ldsm_x4(uint32_t* r, uint32_t saddr) {
    asm volatile(
        "ldmatrix.sync.aligned.m8n8.x4.shared.b16 {%0,%1,%2,%3}, [%4];"
        : "=r"(r[0]), "=r"(r[1]), "=r"(r[2]), "=r"(r[3])
        : "r"(saddr));
}
__device__ __forceinline__ void ldsm_x4_t(uint32_t* r, uint32_t saddr) {
    asm volatile(
        "ldmatrix.sync.aligned.m8n8.x4.trans.shared.b16 {%0,%1,%2,%3}, [%4];"
        : "=r"(r[0]), "=r"(r[1]), "=r"(r[2]), "=r"(r[3])
        : "r"(saddr));
}

__device__ __forceinline__ uint32_t pack_h2(float lo, float hi) {
    __half2 h = __floats2half2_rn(lo, hi);
    return *reinterpret_cast<uint32_t*>(&h);
}

#define CP16(dst, src) \
    asm volatile("cp.async.cg.shared.global [%0], [%1], 16;" \
                 :: "r"(dst), "l"(src))
#define CP_COMMIT() asm volatile("cp.async.commit_group;" ::: "memory")
#define CP_WAIT(n)  asm volatile("cp.async.wait_group %0;" :: "n"(n) : "memory")

// ---------------------------------------------------------------------------
// Pre-convert: states + 4 weights -> fp16.
// ---------------------------------------------------------------------------
__global__ void __launch_bounds__(256) convert_inputs(
    const float* __restrict__ states,
    const float* __restrict__ Wq, const float* __restrict__ Wk,
    const float* __restrict__ Wv, const float* __restrict__ Wo)
{
    size_t idx = (size_t)blockIdx.x * blockDim.x + threadIdx.x;  // float4 idx
    const float* src;
    __half* dst;
    size_t off;
    if (idx < 1048576) {
        src = states; dst = g_a16; off = idx;
    } else {
        size_t j = idx - 1048576;
        int w = (int)(j >> 18);
        off = j & 262143;
        src = (w == 0) ? Wq : (w == 1) ? Wk : (w == 2) ? Wv : Wo;
        dst = g_w16 + (size_t)w * 1048576;
    }
    float4 v = *(const float4*)(src + off * 4);
    uint2 u = make_uint2(pack_h2(v.x, v.y), pack_h2(v.z, v.w));
    *(uint2*)(dst + off * 4) = u;
}

// ---------------------------------------------------------------------------
// FP16 tensor-core GEMM: C = tanh(A @ W + bias).
// CTA tile 128x128, K-step 64, 3-stage cp.async, 8 warps (2x4) 64x32.
// A frags: ldmatrix.x4 (stride 72 halfs = 16B phase mod 128, conflict-free).
// B frags: ldmatrix.x4.trans on [k][n] tile (stride 136 halfs).
// ---------------------------------------------------------------------------
#define ASTR 72
#define BSTR 136
#define STAGES 3
#define KSTEP 64
#define A_STG (128 * ASTR)               // halfs (18432 B)
#define B_STG (KSTEP * BSTR)             // halfs (17408 B)
#define GEMM_SMEM (STAGES * (A_STG + B_STG) * 2)   // 107520 B

template<int MODE>
__global__ void __launch_bounds__(256, 2) gemm_f16_bias_tanh(
    const __half* __restrict__ Abase,
    const float* __restrict__ bq, const float* __restrict__ bk,
    const float* __restrict__ bv,
    float* __restrict__ outO)
{
    extern __shared__ __half hsm[];
    const uint32_t smA_u = smem_u32(hsm);
    const uint32_t smB_u = smA_u + STAGES * A_STG * 2;

    const __half* W;
    const float* bias;
    __half* outq;
    if (MODE == 0) {
        int z = blockIdx.z;
        W    = g_w16 + (size_t)z * (DM * DM);
        bias = (z == 0) ? bq : (z == 1) ? bk : bv;
        outq = (z == 0) ? g_q : (z == 1) ? g_k : g_v;
    } else {
        W = g_w16 + (size_t)3 * (DM * DM);
        bias = bq;
        outq = nullptr;
    }

    const int tid  = threadIdx.x;
    const int wid  = tid >> 5;
    const int lane = tid & 31;
    const int grp  = lane >> 2;
    const int q    = lane & 3;
    const int wm   = wid & 1;
    const int wn   = wid >> 1;

    const int bm = blockIdx.y * 128;
    const int bn = blockIdx.x * 128;

    // Staging: A 128x64 halfs = 1024 chunks; B 64x128 halfs = 1024 chunks.
    // 4 chunks each per thread per tile.
    const __half* aPtr[4];
    const __half* bPtr[4];
    uint32_t aSm[4], bSm[4];
    #pragma unroll
    for (int it = 0; it < 4; it++) {
        int c = tid + 256 * it;
        int ar = c >> 3, ac8 = (c & 7) * 8;          // A: 128 rows x 8 chunks
        aPtr[it] = Abase + (size_t)(bm + ar) * DM + ac8;
        aSm[it]  = (uint32_t)((ar * ASTR + ac8) * 2);
        int br = c >> 4, bc8 = (c & 15) * 8;          // B: 64 rows x 16 chunks
        bPtr[it] = W + (size_t)br * DM + bn + bc8;
        bSm[it]  = (uint32_t)((br * BSTR + bc8) * 2);
    }

    // ldmatrix lane addresses
    const uint32_t aFragOff = (uint32_t)(((wm * 64 + (lane & 15)) * ASTR
                                          + (lane >> 4) * 8) * 2);
    const uint32_t bLaneOff = (uint32_t)(((((lane >> 3) & 1) * 8 + (lane & 7)) * BSTR
                                          + (lane >> 4) * 8) * 2);

    float acc[4][4][4];
    #pragma unroll
    for (int i = 0; i < 4; i++)
        #pragma unroll
        for (int j = 0; j < 4; j++)
            #pragma unroll
            for (int r = 0; r < 4; r++) acc[i][j][r] = 0.f;

    // Prologue: stages 0,1
    #pragma unroll
    for (int s = 0; s < STAGES - 1; s++) {
        const int k0 = s * KSTEP;
        uint32_t aB = smA_u + (uint32_t)(s * A_STG * 2);
        uint32_t bB = smB_u + (uint32_t)(s * B_STG * 2);
        #pragma unroll
        for (int it = 0; it < 4; it++) {
            CP16(aB + aSm[it], aPtr[it] + k0);
            CP16(bB + bSm[it], bPtr[it] + (size_t)k0 * DM);
        }
        CP_COMMIT();
    }

    const int NITER = DM / KSTEP;   // 16
    for (int i = 0; i < NITER; i++) {
        CP_WAIT(1);
        __syncthreads();

        int pre = i + STAGES - 1;
        if (pre < NITER) {
            int s = pre % STAGES;
            const int k0 = pre * KSTEP;
            uint32_t aB = smA_u + (uint32_t)(s * A_STG * 2);
            uint32_t bB = smB_u + (uint32_t)(s * B_STG * 2);
            #pragma unroll
            for (int it = 0; it < 4; it++) {
                CP16(aB + aSm[it], aPtr[it] + k0);
                CP16(bB + bSm[it], bPtr[it] + (size_t)k0 * DM);
            }
        }
        CP_COMMIT();

        const int st = i % STAGES;
        const uint32_t aAddr = smA_u + (uint32_t)(st * A_STG * 2) + aFragOff;
        const uint32_t bAddr = smB_u + (uint32_t)(st * B_STG * 2) + bLaneOff;
        #pragma unroll
        for (int kk = 0; kk < KSTEP; kk += 16) {
            uint32_t af[4][4];
            #pragma unroll
            for (int im = 0; im < 4; im++)
                ldsm_x4(af[im], aAddr + (uint32_t)((im * 16 * ASTR + kk) * 2));
            uint32_t bf[2][4];
            #pragma unroll
            for (int hh = 0; hh < 2; hh++)
                ldsm_x4_t(bf[hh], bAddr + (uint32_t)((kk * BSTR
                                   + wn * 32 + hh * 16) * 2));
            #pragma unroll
            for (int im = 0; im < 4; im++) {
                mma_f16(acc[im][0], af[im], bf[0][0], bf[0][1]);
                mma_f16(acc[im][1], af[im], bf[0][2], bf[0][3]);
                mma_f16(acc[im][2], af[im], bf[1][0], bf[1][1]);
                mma_f16(acc[im][3], af[im], bf[1][2], bf[1][3]);
            }
        }
    }

    #pragma unroll
    for (int im = 0; im < 4; im++) {
        #pragma unroll
        for (int in_ = 0; in_ < 4; in_++) {
            int n0 = bn + wn * 32 + in_ * 8 + 2 * q;
            float b0v = bias[n0], b1v = bias[n0 + 1];
            #pragma unroll
            for (int half = 0; half < 2; half++) {
                int m = bm + wm * 64 + im * 16 + grp + half * 8;
                float y0 = tanhf(acc[im][in_][half * 2 + 0] + b0v);
                float y1 = tanhf(acc[im][in_][half * 2 + 1] + b1v);
                if (MODE == 0) {
                    int bbi = m >> 11;
                    int s   = m & 2047;
                    int h0  = n0 >> 6;
                    int d0  = n0 & 63;
                    size_t base = (((size_t)bbi * NH + h0) * SS + s) * HD + d0;
                    *reinterpret_cast<__half2*>(&outq[base]) =
                        __floats2half2_rn(y0, y1);
                } else {
                    outO[(size_t)m * DM + n0]     = y0;
                    outO[(size_t)m * DM + n0 + 1] = y1;
                }
            }
        }
    }
}

// ---------------------------------------------------------------------------
// FP16 causal flash attention. Double-buffered 128-row K/V tiles via
// cp.async; each tile computed as two 64-row halves between ONE sync pair.
// S = Q@K^T m16n8k16; P packs from S C-frag; V frags via ldmatrix.trans.
// Smem = Q[128] + 2x(K[128]+V[128]) @ stride 72 = 90KB -> 2 CTAs/SM.
// ---------------------------------------------------------------------------
#define QSTR 72
#define KVSTR 72
#define Q_H (128 * QSTR)
#define KV_H (128 * KVSTR)
#define SMEM_ATTN ((Q_H + 4 * KV_H) * 2)

__global__ void __launch_bounds__(256, 2) flash_attn_f16()
{
    extern __shared__ __half smh[];

    const int tid  = threadIdx.x;
    const int wid  = tid >> 5;
    const int lane = tid & 31;
    const int grp  = lane >> 2;
    const int qq   = lane & 3;
    const int qt   = (gridDim.x - 1) - blockIdx.x;
    const int h    = blockIdx.y;
    const int b    = blockIdx.z;
    const int q0   = qt * 128;
    const int mb   = wid * 16;

    const size_t head_off = ((size_t)(b * NH + h)) * SS * HD;
    const __half* Qg = g_q + head_off;
    const __half* Kg = g_k + head_off;
    const __half* Vg = g_v + head_off;

    const uint32_t sbase = smem_u32(smh);
    const uint32_t kBuf[2] = { sbase + Q_H * 2, sbase + (Q_H + KV_H) * 2 };
    const uint32_t vBuf[2] = { sbase + (Q_H + 2 * KV_H) * 2,
                               sbase + (Q_H + 3 * KV_H) * 2 };

    const uint32_t qLane = sbase + (uint32_t)(((mb + (lane & 15)) * QSTR
                                               + (lane >> 4) * 8) * 2);
    const uint32_t kLaneOff = (uint32_t)(((((lane >> 4) & 1) * 8 + (lane & 7)) * KVSTR
                                          + ((lane >> 3) & 1) * 8) * 2);
    const uint32_t vLaneOff = (uint32_t)(((((lane >> 3) & 1) * 8 + (lane & 7)) * KVSTR
                                          + (lane >> 4) * 8) * 2);

    for (int i = tid; i < 1024; i += 256) {
        int r = i >> 3, c8 = (i & 7) * 8;
        CP16(sbase + (uint32_t)((r * QSTR + c8) * 2),
             Qg + (size_t)(q0 + r) * HD + c8);
    }
    CP_COMMIT();

    for (int i = tid; i < 1024; i += 256) {
        int r = i >> 3, c8 = (i & 7) * 8;
        const size_t src = (size_t)r * HD + c8;
        CP16(kBuf[0] + (uint32_t)((r * KVSTR + c8) * 2), Kg + src);
        CP16(vBuf[0] + (uint32_t)((r * KVSTR + c8) * 2), Vg + src);
    }
    CP_COMMIT();

    float m0 = -1e30f, m1 = -1e30f, l0 = 0.f, l1 = 0.f;
    float o[8][4];
    #pragma unroll
    for (int nf = 0; nf < 8; nf++)
        #pragma unroll
        for (int r = 0; r < 4; r++) o[nf][r] = 0.f;

    const int n_kt = qt + 1;
    const int row0 = q0 + mb + grp;
    const int row1 = row0 + 8;

    for (int kt = 0; kt < n_kt; kt++) {
        const int buf = kt & 1;
        const bool has_next = (kt + 1 < n_kt);

        __syncthreads();

        if (has_next) {
            const int r0n = (kt + 1) * 128;
            const int nb = buf ^ 1;
            for (int i = tid; i < 1024; i += 256) {
                int r = i >> 3, c8 = (i & 7) * 8;
                const size_t src = (size_t)(r0n + r) * HD + c8;
                CP16(kBuf[nb] + (uint32_t)((r * KVSTR + c8) * 2), Kg + src);
                CP16(vBuf[nb] + (uint32_t)((r * KVSTR + c8) * 2), Vg + src);
            }
            CP_COMMIT();
            CP_WAIT(1);
        } else {
            CP_WAIT(0);
        }
        __syncthreads();

        #pragma unroll
        for (int hi = 0; hi < 2; hi++) {
            const int k0h = kt * 128 + hi * 64;
            if (k0h > q0 + mb + 15) continue;

            float sc[8][4];
            #pragma unroll
            for (int nf = 0; nf < 8; nf++)
                #pragma unroll
                for (int r = 0; r < 4; r++) sc[nf][r] = 0.f;

            const uint32_t kLane = kBuf[buf] + (uint32_t)(hi * 64 * KVSTR * 2)
                                 + kLaneOff;
            #pragma unroll
            for (int kf = 0; kf < 4; kf++) {
                uint32_t a[4];
                ldsm_x4(a, qLane + (uint32_t)(kf * 32));
                #pragma unroll
                for (int nf2 = 0; nf2 < 8; nf2 += 2) {
                    uint32_t kb[4];
                    ldsm_x4(kb, kLane + (uint32_t)((nf2 * 8 * KVSTR) * 2 + kf * 32));
                    mma_f16(sc[nf2],     a, kb[0], kb[1]);
                    mma_f16(sc[nf2 + 1], a, kb[2], kb[3]);
                }
            }

            const bool diag = (k0h + 63 > q0 + mb);
            float rm0 = -1e30f, rm1 = -1e30f;
            #pragma unroll
            for (int nf = 0; nf < 8; nf++) {
                int c0 = k0h + nf * 8 + 2 * qq;
                float s0v = sc[nf][0] * 0.125f;
                float s1v = sc[nf][1] * 0.125f;
                float s2v = sc[nf][2] * 0.125f;
                float s3v = sc[nf][3] * 0.125f;
                if (diag) {
                    if (c0     > row0) s0v = -1e30f;
                    if (c0 + 1 > row0) s1v = -1e30f;
                    if (c0     > row1) s2v = -1e30f;
                    if (c0 + 1 > row1) s3v = -1e30f;
                }
                sc[nf][0] = s0v; sc[nf][1] = s1v; sc[nf][2] = s2v; sc[nf][3] = s3v;
                rm0 = fmaxf(rm0, fmaxf(s0v, s1v));
                rm1 = fmaxf(rm1, fmaxf(s2v, s3v));
            }
            #pragma unroll
            for (int off = 1; off <= 2; off <<= 1) {
                rm0 = fmaxf(rm0, __shfl_xor_sync(0xffffffffu, rm0, off));
                rm1 = fmaxf(rm1, __shfl_xor_sync(0xffffffffu, rm1, off));
            }
            float mn0 = fmaxf(m0, rm0);
            float mn1 = fmaxf(m1, rm1);

            float s0 = 0.f, s1 = 0.f;
            #pragma unroll
            for (int nf = 0; nf < 8; nf++) {
                float p0 = __expf(sc[nf][0] - mn0);
                float p1 = __expf(sc[nf][1] - mn0);
                float p2 = __expf(sc[nf][2] - mn1);
                float p3 = __expf(sc[nf][3] - mn1);
                sc[nf][0] = p0; sc[nf][1] = p1; sc[nf][2] = p2; sc[nf][3] = p3;
                s0 += p0 + p1;
                s1 += p2 + p3;
            }
            #pragma unroll
            for (int off = 1; off <= 2; off <<= 1) {
                s0 += __shfl_xor_sync(0xffffffffu, s0, off);
                s1 += __shfl_xor_sync(0xffffffffu, s1, off);
            }
            float a0 = __expf(m0 - mn0);
            float a1 = __expf(m1 - mn1);
            l0 = l0 * a0 + s0;
            l1 = l1 * a1 + s1;
            m0 = mn0; m1 = mn1;
            #pragma unroll
            for (int nf = 0; nf < 8; nf++) {
                o[nf][0] *= a0; o[nf][1] *= a0;
                o[nf][2] *= a1; o[nf][3] *= a1;
            }

            const uint32_t vLane = vBuf[buf] + (uint32_t)(hi * 64 * KVSTR * 2)
                                 + vLaneOff;
            #pragma unroll
            for (int kf = 0; kf < 4; kf++) {
                uint32_t a[4];
                a[0] = pack_h2(sc[2*kf][0],   sc[2*kf][1]);
                a[1] = pack_h2(sc[2*kf][2],   sc[2*kf][3]);
                a[2] = pack_h2(sc[2*kf+1][0], sc[2*kf+1][1]);
                a[3] = pack_h2(sc[2*kf+1][2], sc[2*kf+1][3]);
                #pragma unroll
                for (int nf2 = 0; nf2 < 8; nf2 += 2) {
                    uint32_t vb[4];
                    ldsm_x4_t(vb, vLane + (uint32_t)((kf * 16 * KVSTR + nf2 * 8) * 2));
                    mma_f16(o[nf2],     a, vb[0], vb[1]);
                    mma_f16(o[nf2 + 1], a, vb[2], vb[3]);
                }
            }
        }
    }

    float inv0 = 1.f / l0;
    float inv1 = 1.f / l1;
    #pragma unroll
    for (int nf = 0; nf < 8; nf++) {
        int c = h * HD + nf * 8 + 2 * qq;
        *reinterpret_cast<__half2*>(&g_ctx[((size_t)b * SS + row0) * DM + c]) =
            __floats2half2_rn(o[nf][0] * inv0, o[nf][1] * inv0);
        *reinterpret_cast<__half2*>(&g_ctx[((size_t)b * SS + row1) * DM + c]) =
            __floats2half2_rn(o[nf][2] * inv1, o[nf][3] * inv1);
    }
}

// ---------------------------------------------------------------------------
extern "C" void kernel_launch(void* const* d_in, const int* in_sizes, int n_in,
                              void* d_out, int out_size)
{
    const float* states = (const float*)d_in[0];
    const float* Wq = (const float*)d_in[1];
    const float* bq = (const float*)d_in[2];
    const float* Wk = (const float*)d_in[3];
    const float* bk = (const float*)d_in[4];
    const float* Wv = (const float*)d_in[5];
    const float* bv = (const float*)d_in[6];
    const float* bo = (const float*)d_in[8];
    float* out = (float*)d_out;

    __half* a16_ptr = nullptr;
    __half* ctx_ptr = nullptr;
    cudaGetSymbolAddress((void**)&a16_ptr, g_a16);
    cudaGetSymbolAddress((void**)&ctx_ptr, g_ctx);

    cudaFuncSetAttribute(gemm_f16_bias_tanh<0>,
                         cudaFuncAttributeMaxDynamicSharedMemorySize, GEMM_SMEM);
    cudaFuncSetAttribute(gemm_f16_bias_tanh<1>,
                         cudaFuncAttributeMaxDynamicSharedMemorySize, GEMM_SMEM);
    cudaFuncSetAttribute(flash_attn_f16,
                         cudaFuncAttributeMaxDynamicSharedMemorySize, SMEM_ATTN);

    // 0) convert inputs to fp16
    convert_inputs<<<8192, 256>>>(states, Wq, Wk, Wv, (const float*)d_in[7]);

    // 1) QKV projections
    dim3 gq(DM / 128, MT / 128, 3);
    gemm_f16_bias_tanh<0><<<gq, 256, GEMM_SMEM>>>(a16_ptr, bq, bk, bv, nullptr);

    // 2) causal flash attention
    dim3 ga(SS / 128, NH, BB);
    flash_attn_f16<<<ga, 256, SMEM_ATTN>>>();

    // 3) output projection
    dim3 go(DM / 128, MT / 128, 1);
    gemm_f16_bias_tanh<1><<<go, 256, GEMM_SMEM>>>(ctx_ptr, bo, nullptr, nullptr, out);
}